// round 8
// baseline (speedup 1.0000x reference)
#include <cuda_runtime.h>
#include <stdint.h>

#define Bn 64
#define Cn 2
#define Nn 16
#define NBINS 256
#define VOX 262144
#define NBC 128

#define THREADS 256
#define BCG 32                 // bc rows per block (lane <-> bc)
#define NBCG 4
#define CHUNK 2048             // voxels per block = 32 j-lines
#define NCHUNK 128             // VOX / CHUNK
#define VOXT 256               // voxels per tile step (8 half-lines)
#define STEPS 8                // CHUNK / VOXT
#define XSTRIDE 260            // floats per row: 16B-aligned, LDS.128 conflict-free
#define CBINS 25               // ax,az in 0..4 -> compact bin = ax*5+az
#define HSTRIDE 33             // hist row stride, conflict-free deposits
#define MAXSEG 12
#define NHALF 64               // half-lines per chunk

#define XSBUF_F (BCG*XSTRIDE)          // 8320 floats / buffer
#define HIST_F  (8*BCG*HSTRIDE)        // 8448 floats
// xs(2 buf) + hist + masks(64 u32) + segb(768 B) + mags(2048 f)
#define SMEM_BYTES (2*XSBUF_F*4 + HIST_F*4 + NHALF*4 + NHALF*MAXSEG + CHUNK*4)

__device__ float g_scratch[NBC * NBINS];   // zero at load; apply re-zeroes
__device__ float g_coef[2 * Cn];

// Stage one 256-voxel tile for 32 bc rows via 16B cp.async (8 ops/thread).
__device__ __forceinline__ void stage(const float* __restrict__ x, int bc0, int v0,
                                      float* dst, int tid) {
    #pragma unroll
    for (int i = 0; i < 8; i++) {
        int lin = tid + i * THREADS;       // 0..2047 : 16B units
        int row = lin >> 6;                // 32 rows x 64 units
        int u   = lin & 63;
        const float* g = x + (size_t)(bc0 + row) * VOX + v0 + u * 4;
        unsigned s = (unsigned)__cvta_generic_to_shared(dst + row * XSTRIDE + u * 4);
        asm volatile("cp.async.cg.shared.global [%0], [%1], 16;\n" :: "r"(s), "l"(g));
    }
}

// One warp: one half-line (32 k) for 32 bc rows (lane = bc). mask/segbins are
// warp-uniform; x and mag read as float4; deposits conflict-free SMEM RMW.
__device__ __forceinline__ void process_half(const float* __restrict__ xrow,
                                             const float* __restrict__ magrow,
                                             unsigned mask,
                                             const unsigned char* __restrict__ sb,
                                             float* __restrict__ hrow) {
    float run = 0.f;
    int seg = 0;
    int cb = sb[0];
    #pragma unroll
    for (int q = 0; q < 8; q++) {
        float4 xv = *(const float4*)(xrow + q * 4);           // lane-striped, CF
        float4 mg = *(const float4*)(magrow + q * 4);         // broadcast
        float xe[4] = { xv.x, xv.y, xv.z, xv.w };
        float me[4] = { mg.x, mg.y, mg.z, mg.w };
        #pragma unroll
        for (int e = 0; e < 4; e++) {
            int k = q * 4 + e;
            if (k > 0 && ((mask >> k) & 1u)) {                // warp-uniform
                hrow[cb] += run;
                run = 0.f;
                cb = sb[++seg];
            }
            run = fmaf(xe[e], me[e], run);
        }
    }
    hrow[cb] += run;
}

__global__ void __launch_bounds__(THREADS, 2) accum_kernel(const float* __restrict__ x) {
    extern __shared__ float sm[];
    float* xs   = sm;                                  // 2 * XSBUF_F
    float* hist = sm + 2 * XSBUF_F;                    // HIST_F
    unsigned* masks = (unsigned*)(hist + HIST_F);      // NHALF
    unsigned char* segb = (unsigned char*)(masks + NHALF);  // NHALF*MAXSEG
    float* mags = (float*)(segb + NHALF * MAXSEG);     // CHUNK

    const int tid  = threadIdx.x;
    const int w    = tid >> 5, lane = tid & 31;
    const int chunk0 = blockIdx.x * CHUNK;
    const int bc0    = blockIdx.y * BCG;

    // Prefetch tile 0 while computing per-chunk geometry (overlaps DRAM latency).
    stage(x, bc0, chunk0, xs, tid);
    asm volatile("cp.async.commit_group;\n" ::: "memory");

    // Geometry: each warp handles one 32-voxel half-line per pass (8 passes).
    #pragma unroll 1
    for (int t = tid; t < CHUNK; t += THREADS) {
        int v = chunk0 + t;
        float fi = (float)(v >> 12);
        float fj = (float)((v >> 6) & 63);
        float fk = (float)(v & 63);
        mags[t] = sqrtf(fi * fi + fj * fj + fk * fk);
        float xc = sqrtf(fj * fj + fk * fk);
        float zc = sqrtf(fj * fj + fi * fi);
        const float DEG = 57.29577951308232f;   // 180/pi
        int ax = (int)floorf(atan2f(xc, fi) * DEG / 22.0f);
        int az = (int)floorf(atan2f(fk, zc) * DEG / 22.0f);
        int cb = ax * 5 + az;

        int prev = __shfl_up_sync(0xffffffffu, cb, 1);
        bool bnd = (lane > 0) && (cb != prev);
        unsigned mask = __ballot_sync(0xffffffffu, bnd);
        int h = t >> 5;
        if (lane == 0) {
            masks[h] = mask;
            segb[h * MAXSEG] = (unsigned char)cb;
        }
        if (bnd)
            segb[h * MAXSEG + __popc(mask & ((1u << lane) - 1u)) + 1] = (unsigned char)cb;
    }
    for (int i = tid; i < HIST_F; i += THREADS) hist[i] = 0.f;
    __syncthreads();

    float* hrow = hist + (w * BCG + lane) * HSTRIDE;

    #pragma unroll 1
    for (int s = 0; s < STEPS; s++) {
        if (s + 1 < STEPS) {
            stage(x, bc0, chunk0 + (s + 1) * VOXT, xs + ((s + 1) & 1) * XSBUF_F, tid);
            asm volatile("cp.async.commit_group;\n" ::: "memory");
            asm volatile("cp.async.wait_group 1;\n" ::: "memory");
        } else {
            asm volatile("cp.async.wait_group 0;\n" ::: "memory");
        }
        __syncthreads();

        const int h = s * 8 + w;                 // half-line index in chunk
        const float* xrow   = xs + (s & 1) * XSBUF_F + lane * XSTRIDE + w * 32;
        const float* magrow = mags + h * 32;
        process_half(xrow, magrow, masks[h], segb + h * MAXSEG, hrow);
        __syncthreads();
    }

    // Reduce 8 per-warp histograms, flush live bins to global.
    for (int idx = tid; idx < BCG * CBINS; idx += THREADS) {
        int bcl = idx / CBINS;
        int cb  = idx - bcl * CBINS;
        float s = 0.f;
        #pragma unroll
        for (int w2 = 0; w2 < 8; w2++) s += hist[(w2 * BCG + bcl) * HSTRIDE + cb];
        int ax = cb / 5;
        int bin = ax * Nn + (cb - ax * 5);
        if (s != 0.f) atomicAdd(&g_scratch[(bc0 + bcl) * NBINS + bin], s);
    }
}

// Stats + finalize in ONE kernel: block = channel, fp64 reduction over 16384
// values, tid 0 writes scale/shift coefficients.
__global__ void stats_kernel(const float* __restrict__ gamma,
                             const float* __restrict__ beta) {
    const int c = blockIdx.x, tid = threadIdx.x;
    const int M = Bn * NBINS;   // 16384
    __shared__ double red[2][8];

    double s = 0.0, s2 = 0.0;
    for (int idx = tid; idx < M; idx += THREADS) {
        int b = idx >> 8, n = idx & 255;
        double v = (double)g_scratch[(b * Cn + c) * NBINS + n];
        s += v; s2 += v * v;
    }
    #pragma unroll
    for (int o = 16; o; o >>= 1) {
        s  += __shfl_down_sync(0xffffffffu, s,  o);
        s2 += __shfl_down_sync(0xffffffffu, s2, o);
    }
    if ((tid & 31) == 0) { red[0][tid >> 5] = s; red[1][tid >> 5] = s2; }
    __syncthreads();
    if (tid == 0) {
        double t = 0.0, t2 = 0.0;
        #pragma unroll
        for (int i = 0; i < 8; i++) { t += red[0][i]; t2 += red[1][i]; }
        double mean = t / (double)M;
        double var  = t2 / (double)M - mean * mean;
        double rs   = 1.0 / sqrt(var + 1e-5);
        float scale = (float)rs * gamma[c];
        g_coef[2 * c]     = scale;
        g_coef[2 * c + 1] = beta[c] - (float)mean * scale;
    }
}

// Apply affine, write out, re-zero g_scratch (keeps zero-invariant per replay).
__global__ void apply_kernel(float* __restrict__ out) {
    int idx = blockIdx.x * blockDim.x + threadIdx.x;   // 0..32767
    int c = (idx >> 8) & (Cn - 1);
    out[idx] = g_scratch[idx] * g_coef[2 * c] + g_coef[2 * c + 1];
    g_scratch[idx] = 0.f;
}

extern "C" void kernel_launch(void* const* d_in, const int* in_sizes, int n_in,
                              void* d_out, int out_size) {
    const float* x     = (const float*)d_in[0];
    const float* gamma = (const float*)d_in[1];
    const float* beta  = (const float*)d_in[2];
    float* out = (float*)d_out;

    cudaFuncSetAttribute(accum_kernel,
                         cudaFuncAttributeMaxDynamicSharedMemorySize, SMEM_BYTES);
    dim3 grid(NCHUNK, NBCG);
    accum_kernel<<<grid, THREADS, SMEM_BYTES>>>(x);
    stats_kernel<<<Cn, THREADS>>>(gamma, beta);
    apply_kernel<<<NBC * NBINS / 256, 256>>>(out);
}

// round 9
// speedup vs baseline: 2.1798x; 2.1798x over previous
#include <cuda_runtime.h>
#include <stdint.h>

#define Bn 64
#define Cn 2
#define Nn 16
#define NBINS 256
#define VOX 262144
#define NBC 128

#define THREADS 256
#define BCG 32                 // bc rows per block (lane <-> bc)
#define NBCG 4
#define CHUNK 2048             // voxels per block = 32 j-lines
#define NCHUNK 128             // VOX / CHUNK
#define VOXT 128               // voxels per tile step (4 half-lines)
#define STEPS 16               // CHUNK / VOXT
#define XSTRIDE 132            // floats per row: 16B-aligned, %32==4 -> LDS.128 CF
#define CBINS 25               // ax,az in 0..4 -> compact bin = ax*5+az
#define HSTRIDE 33             // hist row stride, lane-distinct banks
#define MAXSEG 12
#define NHALF 64               // half-lines per chunk
#define NHALF_TOT (VOX/32)     // 8192

#define XSBUF_F (BCG*XSTRIDE)          // 4224 floats / buffer
#define HIST_F  (BCG*HSTRIDE)          // 1056 floats (single copy, shared atomics)
// xs(2) + hist + masks(64 u32) + segb(768 B) + mags(2048 f)
#define SMEM_BYTES (2*XSBUF_F*4 + HIST_F*4 + NHALF*4 + NHALF*MAXSEG + CHUNK*4)

__device__ float  g_scratch[NBC * NBINS];   // zero at load; apply re-zeroes
__device__ double g_part[16][Cn][2];        // per-slice stats (overwritten each launch)
__device__ unsigned      g_masks[NHALF_TOT];
__device__ unsigned char g_segb[NHALF_TOT * MAXSEG];
__device__ float         g_mag[VOX];

// One-time geometry per launch: per-voxel bin via atan2 (computed ONCE),
// half-line boundary masks via ballot, segment-bin lists, mag table.
__global__ void __launch_bounds__(THREADS) table_kernel() {
    int v = blockIdx.x * THREADS + threadIdx.x;
    int lane = threadIdx.x & 31;
    float fi = (float)(v >> 12);
    float fj = (float)((v >> 6) & 63);
    float fk = (float)(v & 63);
    g_mag[v] = sqrtf(fi * fi + fj * fj + fk * fk);
    float xc = sqrtf(fj * fj + fk * fk);
    float zc = sqrtf(fj * fj + fi * fi);
    const float DEG = 57.29577951308232f;   // 180/pi
    int ax = (int)floorf(atan2f(xc, fi) * DEG / 22.0f);
    int az = (int)floorf(atan2f(fk, zc) * DEG / 22.0f);
    int cb = ax * 5 + az;

    int prev = __shfl_up_sync(0xffffffffu, cb, 1);
    bool bnd = (lane > 0) && (cb != prev);
    unsigned mask = __ballot_sync(0xffffffffu, bnd);
    int h = v >> 5;
    if (lane == 0) {
        g_masks[h] = mask;
        g_segb[h * MAXSEG] = (unsigned char)cb;
    }
    if (bnd)
        g_segb[h * MAXSEG + __popc(mask & ((1u << lane) - 1u)) + 1] = (unsigned char)cb;
}

// Stage one 128-voxel tile for 32 bc rows via 16B cp.async (4 ops/thread).
// Each warp stages one full row (512B contiguous in global).
__device__ __forceinline__ void stage(const float* __restrict__ x, int bc0, int v0,
                                      float* dst, int tid) {
    #pragma unroll
    for (int i = 0; i < 4; i++) {
        int lin = tid + i * THREADS;       // 0..1023 : 16B units
        int row = lin >> 5;                // 32 rows x 32 units
        int u   = lin & 31;
        const float* g = x + (size_t)(bc0 + row) * VOX + v0 + u * 4;
        unsigned s = (unsigned)__cvta_generic_to_shared(dst + row * XSTRIDE + u * 4);
        asm volatile("cp.async.cg.shared.global [%0], [%1], 16;\n" :: "r"(s), "l"(g));
    }
}

__global__ void __launch_bounds__(THREADS, 4) accum_kernel(const float* __restrict__ x) {
    extern __shared__ float sm[];
    float* xs   = sm;                                  // 2 * XSBUF_F
    float* hist = sm + 2 * XSBUF_F;                    // HIST_F (single copy)
    unsigned* masks = (unsigned*)(hist + HIST_F);      // NHALF
    unsigned char* segb = (unsigned char*)(masks + NHALF);  // NHALF*MAXSEG
    float* mags = (float*)(segb + NHALF * MAXSEG);     // CHUNK

    const int tid  = threadIdx.x;
    const int w    = tid >> 5, lane = tid & 31;
    const int chunk0 = blockIdx.x * CHUNK;
    const int bc0    = blockIdx.y * BCG;

    // Prefetch tile 0, pull precomputed tables (tiny, L2-resident).
    stage(x, bc0, chunk0, xs, tid);
    asm volatile("cp.async.commit_group;\n" ::: "memory");

    const int h0 = blockIdx.x * NHALF;
    if (tid < NHALF) masks[tid] = g_masks[h0 + tid];
    if (tid < NHALF * MAXSEG / 4)   // 768 B, 4-aligned (h0*MAXSEG multiple of 768)
        ((unsigned*)segb)[tid] = ((const unsigned*)(g_segb + (size_t)h0 * MAXSEG))[tid];
    #pragma unroll
    for (int i = 0; i < CHUNK / THREADS; i++)
        mags[tid + i * THREADS] = g_mag[chunk0 + tid + i * THREADS];
    for (int i = tid; i < HIST_F; i += THREADS) hist[i] = 0.f;
    __syncthreads();

    float* hrow = hist + lane * HSTRIDE;   // lane-distinct rows; atomics cross-warp

    #pragma unroll 1
    for (int s = 0; s < STEPS; s++) {
        if (s + 1 < STEPS) {
            stage(x, bc0, chunk0 + (s + 1) * VOXT, xs + ((s + 1) & 1) * XSBUF_F, tid);
            asm volatile("cp.async.commit_group;\n" ::: "memory");
            asm volatile("cp.async.wait_group 1;\n" ::: "memory");
        } else {
            asm volatile("cp.async.wait_group 0;\n" ::: "memory");
        }
        __syncthreads();

        // Warp w processes a 16-k piece: half-line h, k offset klo.
        const int h   = s * 4 + (w >> 1);             // half-line index in chunk
        const int klo = (w & 1) * 16;
        const unsigned mask = masks[h];
        const unsigned char* sb = segb + h * MAXSEG;
        int seg = __popc(mask & ((1u << klo) - 1u));  // segments before this piece
        int cb  = sb[seg];

        const float* xrow   = xs + (s & 1) * XSBUF_F + lane * XSTRIDE + (w >> 1) * 32 + klo;
        const float* magrow = mags + h * 32 + klo;

        float run = 0.f;
        #pragma unroll
        for (int q = 0; q < 4; q++) {
            float4 xv = *(const float4*)(xrow + q * 4);      // lane-striped, CF
            float4 mg = *(const float4*)(magrow + q * 4);    // broadcast
            float xe[4] = { xv.x, xv.y, xv.z, xv.w };
            float me[4] = { mg.x, mg.y, mg.z, mg.w };
            #pragma unroll
            for (int e = 0; e < 4; e++) {
                int kk = klo + q * 4 + e;
                if (kk > 0 && ((mask >> kk) & 1u)) {         // warp-uniform
                    atomicAdd(&hrow[cb], run);               // rare; lane-distinct banks
                    run = 0.f;
                    cb = sb[++seg];
                }
                run = fmaf(xe[e], me[e], run);
            }
        }
        atomicAdd(&hrow[cb], run);
        __syncthreads();
    }

    // Flush live bins to global (25 bins x 32 bc).
    for (int idx = tid; idx < BCG * CBINS; idx += THREADS) {
        int bcl = idx / CBINS;
        int cb  = idx - bcl * CBINS;
        float s = hist[bcl * HSTRIDE + cb];
        int ax = cb / 5;
        int bin = ax * Nn + (cb - ax * 5);
        if (s != 0.f) atomicAdd(&g_scratch[(bc0 + bcl) * NBINS + bin], s);
    }
}

// Stats: 32 blocks (channel, slice), each sums 1024 values fp64 into its own
// g_part slot (no atomics, no reset needed — overwritten every launch).
__global__ void stats_kernel() {
    const int c = blockIdx.x & 1, slice = blockIdx.x >> 1, tid = threadIdx.x;
    __shared__ double red[2][8];
    double s = 0.0, s2 = 0.0;
    #pragma unroll
    for (int i = 0; i < 4; i++) {
        int idx = slice * 1024 + i * 256 + tid;       // (b,n) pair index
        int b = idx >> 8, n = idx & 255;
        double v = (double)g_scratch[(b * Cn + c) * NBINS + n];
        s += v; s2 += v * v;
    }
    #pragma unroll
    for (int o = 16; o; o >>= 1) {
        s  += __shfl_down_sync(0xffffffffu, s,  o);
        s2 += __shfl_down_sync(0xffffffffu, s2, o);
    }
    if ((tid & 31) == 0) { red[0][tid >> 5] = s; red[1][tid >> 5] = s2; }
    __syncthreads();
    if (tid == 0) {
        double t = 0.0, t2 = 0.0;
        #pragma unroll
        for (int i = 0; i < 8; i++) { t += red[0][i]; t2 += red[1][i]; }
        g_part[slice][c][0] = t;
        g_part[slice][c][1] = t2;
    }
}

// Apply: each block serves ONE channel (c = blk & 1). First warp reduces the
// 16 partials and computes scale/shift; then affine + write + re-zero scratch.
__global__ void apply_kernel(const float* __restrict__ gamma,
                             const float* __restrict__ beta,
                             float* __restrict__ out) {
    __shared__ float sh_scale, sh_shift;
    const int blk = blockIdx.x, tid = threadIdx.x;
    const int c = blk & 1;

    if (tid < 32) {
        double s  = (tid < 16) ? g_part[tid][c][0] : 0.0;
        double s2 = (tid < 16) ? g_part[tid][c][1] : 0.0;
        #pragma unroll
        for (int o = 8; o; o >>= 1) {
            s  += __shfl_down_sync(0xffffffffu, s,  o);
            s2 += __shfl_down_sync(0xffffffffu, s2, o);
        }
        if (tid == 0) {
            const double M = (double)(Bn * NBINS);
            double mean = s / M;
            double var  = s2 / M - mean * mean;
            double rs   = 1.0 / sqrt(var + 1e-5);
            float scale = (float)rs * gamma[c];
            sh_scale = scale;
            sh_shift = beta[c] - (float)mean * scale;
        }
    }
    __syncthreads();
    int idx = blk * 256 + tid;            // 0..32767
    out[idx] = g_scratch[idx] * sh_scale + sh_shift;
    g_scratch[idx] = 0.f;                 // restore zero-invariant for next replay
}

extern "C" void kernel_launch(void* const* d_in, const int* in_sizes, int n_in,
                              void* d_out, int out_size) {
    const float* x     = (const float*)d_in[0];
    const float* gamma = (const float*)d_in[1];
    const float* beta  = (const float*)d_in[2];
    float* out = (float*)d_out;

    cudaFuncSetAttribute(accum_kernel,
                         cudaFuncAttributeMaxDynamicSharedMemorySize, SMEM_BYTES);
    table_kernel<<<VOX / THREADS, THREADS>>>();
    dim3 grid(NCHUNK, NBCG);
    accum_kernel<<<grid, THREADS, SMEM_BYTES>>>(x);
    stats_kernel<<<32, THREADS>>>();
    apply_kernel<<<NBC * NBINS / 256, 256>>>(gamma, beta, out);
}